// round 1
// baseline (speedup 1.0000x reference)
#include <cuda_runtime.h>
#include <math.h>

#define Bb 2
#define Ll 2048
#define DMM 512
#define Hh 8
#define Dd 64
#define NUMK 40
#define NUMQ 40
#define LN_EPS 1e-5f

// ---------------- scratch (static device globals; no allocs allowed) ----------------
__device__ __align__(256) float g_qp[Bb*Ll*DMM];
__device__ __align__(256) float g_kp[Bb*Ll*DMM];
__device__ __align__(256) float g_vp[Bb*Ll*DMM];
__device__ __align__(256) float g_ctx[Bb*Ll*DMM];
__device__ __align__(256) float g_measure[Bb*Hh*Ll];
__device__ __align__(256) float g_vpart[Bb*16*DMM];
__device__ __align__(256) float g_vmean[Bb*DMM];
__device__ __align__(256) int   g_qidx[Bb*Hh*NUMQ];

// ---------------- projection GEMM: C = A[4096,512] @ W[512,512] + bias ----------------
// 64x64 tile, BK=16, 256 threads, 4x4 per-thread microtile.
__global__ __launch_bounds__(256) void gemm_bias_kernel(
    const float* __restrict__ A, const float* __restrict__ W,
    const float* __restrict__ bias, int which)
{
    float* C = (which == 0) ? g_qp : (which == 1) ? g_kp : g_vp;
    const int K = DMM, N = DMM;
    __shared__ float As[16][64];   // [k][m]
    __shared__ float Ws[16][64];   // [k][n]
    int tid = threadIdx.x;
    int tx = tid & 15, ty = tid >> 4;
    int m0 = blockIdx.y * 64, n0 = blockIdx.x * 64;
    int ar = tid >> 2, ac = tid & 3;     // A loader: row 0..63, float4 col 0..3
    int wr = tid >> 4, wc = tid & 15;    // W loader: k row 0..15, float4 col 0..15
    float acc[4][4];
#pragma unroll
    for (int i = 0; i < 4; i++)
#pragma unroll
        for (int j = 0; j < 4; j++) acc[i][j] = 0.f;

    for (int k0 = 0; k0 < K; k0 += 16) {
        float4 av = *(const float4*)(A + (size_t)(m0 + ar) * K + k0 + ac * 4);
        float4 wv = *(const float4*)(W + (size_t)(k0 + wr) * N + n0 + wc * 4);
        __syncthreads();
        As[ac*4+0][ar] = av.x; As[ac*4+1][ar] = av.y;
        As[ac*4+2][ar] = av.z; As[ac*4+3][ar] = av.w;
        *(float4*)&Ws[wr][wc*4] = wv;
        __syncthreads();
#pragma unroll
        for (int k = 0; k < 16; k++) {
            float4 a = *(float4*)&As[k][ty*4];
            float4 b = *(float4*)&Ws[k][tx*4];
            acc[0][0] += a.x*b.x; acc[0][1] += a.x*b.y; acc[0][2] += a.x*b.z; acc[0][3] += a.x*b.w;
            acc[1][0] += a.y*b.x; acc[1][1] += a.y*b.y; acc[1][2] += a.y*b.z; acc[1][3] += a.y*b.w;
            acc[2][0] += a.z*b.x; acc[2][1] += a.z*b.y; acc[2][2] += a.z*b.z; acc[2][3] += a.z*b.w;
            acc[3][0] += a.w*b.x; acc[3][1] += a.w*b.y; acc[3][2] += a.w*b.z; acc[3][3] += a.w*b.w;
        }
    }
#pragma unroll
    for (int i = 0; i < 4; i++) {
        int m = m0 + ty*4 + i;
#pragma unroll
        for (int j = 0; j < 4; j++) {
            int n = n0 + tx*4 + j;
            C[(size_t)m * N + n] = acc[i][j] + bias[n];
        }
    }
}

// ---------------- v_mean (two-stage, deterministic) ----------------
__global__ void vmean_part_kernel() {
    int blk = blockIdx.x;             // Bb*16
    int b = blk >> 4, j = blk & 15;
    int c = threadIdx.x;              // 512
    float s = 0.f;
    int base = j * 128;
    for (int l = base; l < base + 128; l++) s += g_vp[((size_t)b*Ll + l)*DMM + c];
    g_vpart[(size_t)blk*DMM + c] = s;
}
__global__ void vmean_reduce_kernel() {
    int b = blockIdx.x; int c = threadIdx.x;
    float s = 0.f;
    for (int j = 0; j < 16; j++) s += g_vpart[((size_t)b*16 + j)*DMM + c];
    g_vmean[b*DMM + c] = s * (1.0f / Ll);
}

// ---------------- fill context with broadcast v_mean ----------------
__global__ void fill_ctx_kernel() {
    int idx = blockIdx.x * blockDim.x + threadIdx.x;   // covers Bb*Ll*DMM
    int c = idx & (DMM - 1);
    int b = idx >> 20;                                  // Ll*DMM = 2^20
    g_ctx[idx] = g_vmean[b*DMM + c];
}

// ---------------- pre + measure: one warp per (b,h,l) ----------------
__global__ __launch_bounds__(256) void measure_kernel(const int* __restrict__ ridx) {
    int gw = (blockIdx.x * blockDim.x + threadIdx.x) >> 5;
    int lane = threadIdx.x & 31;
    if (gw >= Bb*Hh*Ll) return;
    int l = gw % Ll;
    int h = (gw / Ll) % Hh;
    int b = gw / (Ll * Hh);
    const float* qrow = &g_qp[((size_t)b*Ll + l)*DMM + h*Dd];
    float2 qv = *(const float2*)&qrow[lane*2];
    float mx = -INFINITY, sm = 0.f;
#pragma unroll 4
    for (int j = 0; j < NUMK; j++) {
        int ki = ridx[l*NUMK + j];
        const float* krow = &g_kp[((size_t)b*Ll + ki)*DMM + h*Dd];
        float2 kv = *(const float2*)&krow[lane*2];
        float p = qv.x*kv.x + qv.y*kv.y;
#pragma unroll
        for (int o = 16; o; o >>= 1) p += __shfl_xor_sync(0xffffffffu, p, o);
        mx = fmaxf(mx, p);
        sm += p;
    }
    if (lane == 0) g_measure[gw] = mx - sm * (1.0f / Ll);
}

// ---------------- exact top-40 per (b,h), jax.lax.top_k ordering ----------------
__global__ __launch_bounds__(256) void topk_kernel() {
    __shared__ float vals[Ll];
    __shared__ float rv[256];
    __shared__ int   ri[256];
    int bh = blockIdx.x;
    int t = threadIdx.x;
    for (int i = t; i < Ll; i += 256) vals[i] = g_measure[(size_t)bh*Ll + i];
    __syncthreads();
    for (int s = 0; s < NUMQ; s++) {
        float bv = -INFINITY; int bi = 0x7fffffff;
        for (int i = t; i < Ll; i += 256) {
            float v = vals[i];
            if (v > bv || (v == bv && i < bi)) { bv = v; bi = i; }
        }
        rv[t] = bv; ri[t] = bi;
        __syncthreads();
        for (int off = 128; off; off >>= 1) {
            if (t < off) {
                if (rv[t+off] > rv[t] || (rv[t+off] == rv[t] && ri[t+off] < ri[t])) {
                    rv[t] = rv[t+off]; ri[t] = ri[t+off];
                }
            }
            __syncthreads();
        }
        if (t == 0) { g_qidx[bh*NUMQ + s] = ri[0]; vals[ri[0]] = -INFINITY; }
        __syncthreads();
    }
}

// ---------------- attention: block per (b,h,selected-q) ----------------
__global__ __launch_bounds__(256) void attn_kernel(float* __restrict__ out_attn) {
    int blk = blockIdx.x;                       // ((b*H+h)*NUMQ + t)
    int t = blk % NUMQ;
    int h = (blk / NUMQ) % Hh;
    int b = blk / (NUMQ * Hh);
    __shared__ float qs[Dd];
    __shared__ float sc[Ll];
    __shared__ float red[8];
    __shared__ float pv[4][Dd];
    int tid = threadIdx.x;
    int lane = tid & 31, w = tid >> 5;
    int qi = g_qidx[(b*Hh + h)*NUMQ + t];
    if (tid < Dd) qs[tid] = g_qp[((size_t)b*Ll + qi)*DMM + h*Dd + tid];
    __syncthreads();
    const float scale = 0.125f;   // D^-0.5
    // scores: warp per key row
    for (int j = w; j < Ll; j += 8) {
        const float* krow = &g_kp[((size_t)b*Ll + j)*DMM + h*Dd];
        float2 kv = *(const float2*)&krow[lane*2];
        float p = kv.x*qs[lane*2] + kv.y*qs[lane*2+1];
#pragma unroll
        for (int o = 16; o; o >>= 1) p += __shfl_xor_sync(0xffffffffu, p, o);
        if (lane == 0) sc[j] = p * scale;
    }
    __syncthreads();
    // row max
    float m = -INFINITY;
    for (int j = tid; j < Ll; j += 256) m = fmaxf(m, sc[j]);
#pragma unroll
    for (int o = 16; o; o >>= 1) m = fmaxf(m, __shfl_xor_sync(0xffffffffu, m, o));
    if (lane == 0) red[w] = m;
    __syncthreads();
    m = fmaxf(fmaxf(fmaxf(red[0],red[1]),fmaxf(red[2],red[3])),
              fmaxf(fmaxf(red[4],red[5]),fmaxf(red[6],red[7])));
    __syncthreads();
    // exp + sum
    float s = 0.f;
    for (int j = tid; j < Ll; j += 256) { float e = expf(sc[j] - m); sc[j] = e; s += e; }
#pragma unroll
    for (int o = 16; o; o >>= 1) s += __shfl_xor_sync(0xffffffffu, s, o);
    if (lane == 0) red[w] = s;
    __syncthreads();
    float tot = red[0]+red[1]+red[2]+red[3]+red[4]+red[5]+red[6]+red[7];
    float inv = 1.0f / tot;
    size_t aoff = (size_t)blk * Ll;
    for (int j = tid; j < Ll; j += 256) {
        float p = sc[j] * inv;
        sc[j] = p;
        out_attn[aoff + j] = p;
    }
    __syncthreads();
    // PV: out[d] = sum_j p[j] * vp[b,j,h*64+d]
    int d = tid & 63, part = tid >> 6;
    float acc = 0.f;
    int j0 = part * 512;
    for (int j = j0; j < j0 + 512; j++)
        acc += sc[j] * g_vp[((size_t)b*Ll + j)*DMM + h*Dd + d];
    pv[part][d] = acc;
    __syncthreads();
    if (part == 0) {
        float r = pv[0][d] + pv[1][d] + pv[2][d] + pv[3][d];
        g_ctx[((size_t)b*Ll + qi)*DMM + h*Dd + d] = r;
    }
}

// ---------------- residual + layernorm ----------------
__global__ __launch_bounds__(256) void ln_kernel(const float* __restrict__ qin,
                                                 const float* __restrict__ gamma,
                                                 const float* __restrict__ beta,
                                                 float* __restrict__ out)
{
    int row = blockIdx.x;     // Bb*Ll
    int tid = threadIdx.x;    // 256
    __shared__ float sm[8], sm2[8];
    const float* ctx = g_ctx + (size_t)row * DMM;
    const float* qr  = qin  + (size_t)row * DMM;
    float v0 = ctx[tid]       + qr[tid];
    float v1 = ctx[tid + 256] + qr[tid + 256];
    int lane = tid & 31, w = tid >> 5;
    float s = v0 + v1;
#pragma unroll
    for (int o = 16; o; o >>= 1) s += __shfl_xor_sync(0xffffffffu, s, o);
    if (lane == 0) sm[w] = s;
    __syncthreads();
    float mean = (sm[0]+sm[1]+sm[2]+sm[3]+sm[4]+sm[5]+sm[6]+sm[7]) * (1.0f / DMM);
    float d0 = v0 - mean, d1 = v1 - mean;
    float s2 = d0*d0 + d1*d1;
#pragma unroll
    for (int o = 16; o; o >>= 1) s2 += __shfl_xor_sync(0xffffffffu, s2, o);
    if (lane == 0) sm2[w] = s2;
    __syncthreads();
    float var = (sm2[0]+sm2[1]+sm2[2]+sm2[3]+sm2[4]+sm2[5]+sm2[6]+sm2[7]) * (1.0f / DMM);
    float invstd = rsqrtf(var + LN_EPS);
    out[(size_t)row*DMM + tid]       = d0 * invstd * gamma[tid]       + beta[tid];
    out[(size_t)row*DMM + tid + 256] = d1 * invstd * gamma[tid + 256] + beta[tid + 256];
}

// ---------------- launch ----------------
extern "C" void kernel_launch(void* const* d_in, const int* in_sizes, int n_in,
                              void* d_out, int out_size)
{
    const float* q     = (const float*)d_in[0];
    const float* k     = (const float*)d_in[1];
    const float* v     = (const float*)d_in[2];
    const float* Wq    = (const float*)d_in[3];
    const float* bq    = (const float*)d_in[4];
    const float* Wk    = (const float*)d_in[5];
    const float* bk    = (const float*)d_in[6];
    const float* Wv    = (const float*)d_in[7];
    const float* bv    = (const float*)d_in[8];
    const float* gamma = (const float*)d_in[9];
    const float* beta  = (const float*)d_in[10];
    const int*   ridx  = (const int*)d_in[11];
    float* out      = (float*)d_out;
    float* out_attn = out + (size_t)Bb * Ll * DMM;   // yn first, then attn

    dim3 gg(DMM / 64, (Bb * Ll) / 64);               // (8, 64)
    gemm_bias_kernel<<<gg, 256>>>(q, Wq, bq, 0);
    gemm_bias_kernel<<<gg, 256>>>(k, Wk, bk, 1);
    gemm_bias_kernel<<<gg, 256>>>(v, Wv, bv, 2);

    vmean_part_kernel<<<Bb * 16, DMM>>>();
    vmean_reduce_kernel<<<Bb, DMM>>>();
    fill_ctx_kernel<<<(Bb * Ll * DMM) / 256, 256>>>();

    measure_kernel<<<(Bb * Hh * Ll) / 8, 256>>>(ridx);
    topk_kernel<<<Bb * Hh, 256>>>();

    attn_kernel<<<Bb * Hh * NUMQ, 256>>>(out_attn);

    ln_kernel<<<Bb * Ll, 256>>>(q, gamma, beta, out);
}

// round 2
// speedup vs baseline: 1.2184x; 1.2184x over previous
#include <cuda_runtime.h>
#include <cuda_bf16.h>
#include <mma.h>
#include <math.h>

using namespace nvcuda;

#define Bb 2
#define Ll 2048
#define DMM 512
#define Hh 8
#define Dd 64
#define NUMK 40
#define NUMQ 40
#define LN_EPS 1e-5f

// ---------------- scratch (static device globals; no allocs allowed) ----------------
__device__ __align__(256) float g_qp[Bb*Ll*DMM];
__device__ __align__(256) float g_kp[Bb*Ll*DMM];
__device__ __align__(256) float g_vp[Bb*Ll*DMM];
__device__ __align__(256) float g_ctx[Bb*Ll*DMM];
__device__ __align__(256) float g_measure[Bb*Hh*Ll];
__device__ __align__(256) float g_vpart[Bb*16*DMM];
__device__ __align__(256) float g_vmean[Bb*DMM];
__device__ __align__(256) int   g_qidx[Bb*Hh*NUMQ];

// bf16 split storage (hi/lo) for tensor-core GEMM
__device__ __align__(256) __nv_bfloat16 g_qh[Bb*Ll*DMM];
__device__ __align__(256) __nv_bfloat16 g_ql[Bb*Ll*DMM];
__device__ __align__(256) __nv_bfloat16 g_kh[Bb*Ll*DMM];
__device__ __align__(256) __nv_bfloat16 g_kl[Bb*Ll*DMM];
__device__ __align__(256) __nv_bfloat16 g_vh[Bb*Ll*DMM];
__device__ __align__(256) __nv_bfloat16 g_vl[Bb*Ll*DMM];
__device__ __align__(256) __nv_bfloat16 g_Wqh[DMM*DMM];
__device__ __align__(256) __nv_bfloat16 g_Wql[DMM*DMM];
__device__ __align__(256) __nv_bfloat16 g_Wkh[DMM*DMM];
__device__ __align__(256) __nv_bfloat16 g_Wkl[DMM*DMM];
__device__ __align__(256) __nv_bfloat16 g_Wvh[DMM*DMM];
__device__ __align__(256) __nv_bfloat16 g_Wvl[DMM*DMM];

// ---------------- fp32 -> (hi, lo) bf16 split, 4 elems/thread ----------------
__global__ void split_kernel(const float* __restrict__ src,
                             __nv_bfloat16* __restrict__ hi,
                             __nv_bfloat16* __restrict__ lo, int n4)
{
    int i = blockIdx.x * blockDim.x + threadIdx.x;
    if (i >= n4) return;
    float4 x = ((const float4*)src)[i];
    __nv_bfloat16 h0 = __float2bfloat16(x.x);
    __nv_bfloat16 h1 = __float2bfloat16(x.y);
    __nv_bfloat16 h2 = __float2bfloat16(x.z);
    __nv_bfloat16 h3 = __float2bfloat16(x.w);
    __nv_bfloat16 l0 = __float2bfloat16(x.x - __bfloat162float(h0));
    __nv_bfloat16 l1 = __float2bfloat16(x.y - __bfloat162float(h1));
    __nv_bfloat16 l2 = __float2bfloat16(x.z - __bfloat162float(h2));
    __nv_bfloat16 l3 = __float2bfloat16(x.w - __bfloat162float(h3));
    ((__nv_bfloat162*)hi)[2*i]   = __nv_bfloat162(h0, h1);
    ((__nv_bfloat162*)hi)[2*i+1] = __nv_bfloat162(h2, h3);
    ((__nv_bfloat162*)lo)[2*i]   = __nv_bfloat162(l0, l1);
    ((__nv_bfloat162*)lo)[2*i+1] = __nv_bfloat162(l2, l3);
}

// ---------------- tensor-core GEMM (3xBF16 split): C = A@W + bias ----------------
// BM=128 BN=64 BK=32, 256 threads (8 warps, 4x2 warp grid, 32x32 warp tiles).
#define LDA 40   // 32 + 8 pad (bf16 elems)
#define LDB 72   // 64 + 8 pad
#define LDC 72   // fp32 epilogue stride
__global__ __launch_bounds__(256) void gemm_tc_kernel(
    const float* __restrict__ bq, const float* __restrict__ bk,
    const float* __restrict__ bv)
{
    int which = blockIdx.z;
    const __nv_bfloat16 *Ah, *Al, *Wh, *Wl;
    const float* bias;
    float* C;
    if (which == 0)      { Ah=g_qh; Al=g_ql; Wh=g_Wqh; Wl=g_Wql; bias=bq; C=g_qp; }
    else if (which == 1) { Ah=g_kh; Al=g_kl; Wh=g_Wkh; Wl=g_Wkl; bias=bk; C=g_kp; }
    else                 { Ah=g_vh; Al=g_vl; Wh=g_Wvh; Wl=g_Wvl; bias=bv; C=g_vp; }

    __shared__ __align__(16) unsigned char sraw[128*LDC*4];  // 36864 B
    __nv_bfloat16* Ahs = (__nv_bfloat16*)sraw;                 // 128*40*2 = 10240
    __nv_bfloat16* Als = (__nv_bfloat16*)(sraw + 10240);       // 10240
    __nv_bfloat16* Bhs = (__nv_bfloat16*)(sraw + 20480);       // 32*72*2 = 4608
    __nv_bfloat16* Bls = (__nv_bfloat16*)(sraw + 25088);       // 4608 -> 29696
    float* Cs = (float*)sraw;                                  // reused in epilogue

    int tid = threadIdx.x;
    int warp = tid >> 5;
    int wm = warp >> 1, wn = warp & 1;
    int m0 = blockIdx.y * 128, n0 = blockIdx.x * 64;

    wmma::fragment<wmma::accumulator, 16,16,16, float> acc[2][2];
#pragma unroll
    for (int i = 0; i < 2; i++)
#pragma unroll
        for (int j = 0; j < 2; j++) wmma::fill_fragment(acc[i][j], 0.f);

    int arow0 = tid >> 2, ac4 = tid & 3;        // A: idx=tid, tid+256
    int brow  = tid >> 3, bc4 = tid & 7;        // B: one uint4/thread/split

    for (int k0 = 0; k0 < DMM; k0 += 32) {
        // stage tiles
        uint4 a0h = *(const uint4*)(Ah + (size_t)(m0 + arow0)*DMM + k0 + ac4*8);
        uint4 a1h = *(const uint4*)(Ah + (size_t)(m0 + arow0 + 64)*DMM + k0 + ac4*8);
        uint4 a0l = *(const uint4*)(Al + (size_t)(m0 + arow0)*DMM + k0 + ac4*8);
        uint4 a1l = *(const uint4*)(Al + (size_t)(m0 + arow0 + 64)*DMM + k0 + ac4*8);
        uint4 bh  = *(const uint4*)(Wh + (size_t)(k0 + brow)*DMM + n0 + bc4*8);
        uint4 bl  = *(const uint4*)(Wl + (size_t)(k0 + brow)*DMM + n0 + bc4*8);
        __syncthreads();
        *(uint4*)(Ahs + arow0*LDA + ac4*8)        = a0h;
        *(uint4*)(Ahs + (arow0+64)*LDA + ac4*8)   = a1h;
        *(uint4*)(Als + arow0*LDA + ac4*8)        = a0l;
        *(uint4*)(Als + (arow0+64)*LDA + ac4*8)   = a1l;
        *(uint4*)(Bhs + brow*LDB + bc4*8)         = bh;
        *(uint4*)(Bls + brow*LDB + bc4*8)         = bl;
        __syncthreads();
#pragma unroll
        for (int ks = 0; ks < 32; ks += 16) {
            wmma::fragment<wmma::matrix_a, 16,16,16, __nv_bfloat16, wmma::row_major> ah[2], al[2];
            wmma::fragment<wmma::matrix_b, 16,16,16, __nv_bfloat16, wmma::row_major> bhf[2], blf[2];
#pragma unroll
            for (int i = 0; i < 2; i++) {
                wmma::load_matrix_sync(ah[i], Ahs + (wm*32 + i*16)*LDA + ks, LDA);
                wmma::load_matrix_sync(al[i], Als + (wm*32 + i*16)*LDA + ks, LDA);
            }
#pragma unroll
            for (int j = 0; j < 2; j++) {
                wmma::load_matrix_sync(bhf[j], Bhs + ks*LDB + wn*32 + j*16, LDB);
                wmma::load_matrix_sync(blf[j], Bls + ks*LDB + wn*32 + j*16, LDB);
            }
#pragma unroll
            for (int i = 0; i < 2; i++)
#pragma unroll
                for (int j = 0; j < 2; j++) {
                    wmma::mma_sync(acc[i][j], ah[i], bhf[j], acc[i][j]);
                    wmma::mma_sync(acc[i][j], ah[i], blf[j], acc[i][j]);
                    wmma::mma_sync(acc[i][j], al[i], bhf[j], acc[i][j]);
                }
        }
    }
    __syncthreads();
#pragma unroll
    for (int i = 0; i < 2; i++)
#pragma unroll
        for (int j = 0; j < 2; j++)
            wmma::store_matrix_sync(Cs + (wm*32 + i*16)*LDC + wn*32 + j*16,
                                    acc[i][j], LDC, wmma::mem_row_major);
    __syncthreads();
    for (int i = tid; i < 128*64; i += 256) {
        int m = i >> 6, n = i & 63;
        C[(size_t)(m0 + m)*DMM + n0 + n] = Cs[m*LDC + n] + bias[n0 + n];
    }
}

// ---------------- v_mean (two-stage, deterministic) ----------------
__global__ void vmean_part_kernel() {
    int blk = blockIdx.x;
    int b = blk >> 4, j = blk & 15;
    int c = threadIdx.x;
    float s = 0.f;
    int base = j * 128;
    for (int l = base; l < base + 128; l++) s += g_vp[((size_t)b*Ll + l)*DMM + c];
    g_vpart[(size_t)blk*DMM + c] = s;
}
__global__ void vmean_reduce_kernel() {
    int b = blockIdx.x; int c = threadIdx.x;
    float s = 0.f;
    for (int j = 0; j < 16; j++) s += g_vpart[((size_t)b*16 + j)*DMM + c];
    g_vmean[b*DMM + c] = s * (1.0f / Ll);
}

__global__ void fill_ctx_kernel() {
    int idx = blockIdx.x * blockDim.x + threadIdx.x;
    int c = idx & (DMM - 1);
    int b = idx >> 20;
    g_ctx[idx] = g_vmean[b*DMM + c];
}

// ---------------- pre + measure: one warp per (b,h,l) ----------------
__global__ __launch_bounds__(256) void measure_kernel(const int* __restrict__ ridx) {
    int gw = (blockIdx.x * blockDim.x + threadIdx.x) >> 5;
    int lane = threadIdx.x & 31;
    if (gw >= Bb*Hh*Ll) return;
    int l = gw % Ll;
    int h = (gw / Ll) % Hh;
    int b = gw / (Ll * Hh);
    const float* qrow = &g_qp[((size_t)b*Ll + l)*DMM + h*Dd];
    float2 qv = *(const float2*)&qrow[lane*2];
    float mx = -INFINITY, sm = 0.f;
#pragma unroll 4
    for (int j = 0; j < NUMK; j++) {
        int ki = ridx[l*NUMK + j];
        const float* krow = &g_kp[((size_t)b*Ll + ki)*DMM + h*Dd];
        float2 kv = *(const float2*)&krow[lane*2];
        float p = qv.x*kv.x + qv.y*kv.y;
#pragma unroll
        for (int o = 16; o; o >>= 1) p += __shfl_xor_sync(0xffffffffu, p, o);
        mx = fmaxf(mx, p);
        sm += p;
    }
    if (lane == 0) g_measure[gw] = mx - sm * (1.0f / Ll);
}

// ---------------- exact top-40 per (b,h), jax.lax.top_k ordering ----------------
__global__ __launch_bounds__(256) void topk_kernel() {
    __shared__ float vals[Ll];
    __shared__ float rv[256];
    __shared__ int   ri[256];
    int bh = blockIdx.x;
    int t = threadIdx.x;
    for (int i = t; i < Ll; i += 256) vals[i] = g_measure[(size_t)bh*Ll + i];
    __syncthreads();
    for (int s = 0; s < NUMQ; s++) {
        float bv = -INFINITY; int bi = 0x7fffffff;
        for (int i = t; i < Ll; i += 256) {
            float v = vals[i];
            if (v > bv || (v == bv && i < bi)) { bv = v; bi = i; }
        }
        rv[t] = bv; ri[t] = bi;
        __syncthreads();
        for (int off = 128; off; off >>= 1) {
            if (t < off) {
                if (rv[t+off] > rv[t] || (rv[t+off] == rv[t] && ri[t+off] < ri[t])) {
                    rv[t] = rv[t+off]; ri[t] = ri[t+off];
                }
            }
            __syncthreads();
        }
        if (t == 0) { g_qidx[bh*NUMQ + s] = ri[0]; vals[ri[0]] = -INFINITY; }
        __syncthreads();
    }
}

// ---------------- attention: block per (b,h,group-of-4-q) ----------------
__global__ __launch_bounds__(256) void attn_kernel(float* __restrict__ out_attn) {
    int blk = blockIdx.x;                       // (b*H+h)*10 + g
    int g = blk % 10;
    int h = (blk / 10) % Hh;
    int b = blk / (10 * Hh);
    __shared__ float qs[4][Dd];
    __shared__ float sc[4][Ll];
    __shared__ float red[8];
    __shared__ float pvs[4][4][Dd];
    __shared__ int qix[4];
    int tid = threadIdx.x;
    int lane = tid & 31, w = tid >> 5;
    if (tid < 4) qix[tid] = g_qidx[(b*Hh + h)*NUMQ + g*4 + tid];
    __syncthreads();
    {
        int qq = tid >> 6, d = tid & 63;
        qs[qq][d] = g_qp[((size_t)b*Ll + qix[qq])*DMM + h*Dd + d];
    }
    __syncthreads();
    const float scale = 0.125f;   // D^-0.5
    // scores: warp per key row, 4 q's at once
    for (int j = w; j < Ll; j += 8) {
        const float2 kv = *(const float2*)&g_kp[((size_t)b*Ll + j)*DMM + h*Dd + lane*2];
        float p0 = kv.x*qs[0][lane*2] + kv.y*qs[0][lane*2+1];
        float p1 = kv.x*qs[1][lane*2] + kv.y*qs[1][lane*2+1];
        float p2 = kv.x*qs[2][lane*2] + kv.y*qs[2][lane*2+1];
        float p3 = kv.x*qs[3][lane*2] + kv.y*qs[3][lane*2+1];
#pragma unroll
        for (int o = 16; o; o >>= 1) {
            p0 += __shfl_xor_sync(0xffffffffu, p0, o);
            p1 += __shfl_xor_sync(0xffffffffu, p1, o);
            p2 += __shfl_xor_sync(0xffffffffu, p2, o);
            p3 += __shfl_xor_sync(0xffffffffu, p3, o);
        }
        if (lane == 0) {
            sc[0][j] = p0 * scale; sc[1][j] = p1 * scale;
            sc[2][j] = p2 * scale; sc[3][j] = p3 * scale;
        }
    }
    __syncthreads();
    // softmax per q + write attn
#pragma unroll
    for (int q = 0; q < 4; q++) {
        float m = -INFINITY;
        for (int j = tid; j < Ll; j += 256) m = fmaxf(m, sc[q][j]);
#pragma unroll
        for (int o = 16; o; o >>= 1) m = fmaxf(m, __shfl_xor_sync(0xffffffffu, m, o));
        if (lane == 0) red[w] = m;
        __syncthreads();
        m = fmaxf(fmaxf(fmaxf(red[0],red[1]),fmaxf(red[2],red[3])),
                  fmaxf(fmaxf(red[4],red[5]),fmaxf(red[6],red[7])));
        __syncthreads();
        float s = 0.f;
        for (int j = tid; j < Ll; j += 256) { float e = expf(sc[q][j] - m); sc[q][j] = e; s += e; }
#pragma unroll
        for (int o = 16; o; o >>= 1) s += __shfl_xor_sync(0xffffffffu, s, o);
        if (lane == 0) red[w] = s;
        __syncthreads();
        float inv = 1.0f / (red[0]+red[1]+red[2]+red[3]+red[4]+red[5]+red[6]+red[7]);
        size_t aoff = ((size_t)(b*Hh + h)*NUMQ + g*4 + q) * Ll;
        for (int j = tid; j < Ll; j += 256) {
            float p = sc[q][j] * inv;
            sc[q][j] = p;
            out_attn[aoff + j] = p;
        }
        __syncthreads();
    }
    // PV: 4 partitions over j, 64 d-threads each, all 4 q's per pass
    int d = tid & 63, part = tid >> 6;
    float a0 = 0.f, a1 = 0.f, a2 = 0.f, a3 = 0.f;
    int j0 = part * 512;
    for (int j = j0; j < j0 + 512; j++) {
        float v = g_vp[((size_t)b*Ll + j)*DMM + h*Dd + d];
        a0 += sc[0][j]*v; a1 += sc[1][j]*v; a2 += sc[2][j]*v; a3 += sc[3][j]*v;
    }
    pvs[part][0][d] = a0; pvs[part][1][d] = a1;
    pvs[part][2][d] = a2; pvs[part][3][d] = a3;
    __syncthreads();
    if (part == 0) {
#pragma unroll
        for (int q = 0; q < 4; q++) {
            float r = pvs[0][q][d] + pvs[1][q][d] + pvs[2][q][d] + pvs[3][q][d];
            g_ctx[((size_t)b*Ll + qix[q])*DMM + h*Dd + d] = r;
        }
    }
}

// ---------------- residual + layernorm ----------------
__global__ __launch_bounds__(256) void ln_kernel(const float* __restrict__ qin,
                                                 const float* __restrict__ gamma,
                                                 const float* __restrict__ beta,
                                                 float* __restrict__ out)
{
    int row = blockIdx.x;
    int tid = threadIdx.x;
    __shared__ float sm[8], sm2[8];
    const float* ctx = g_ctx + (size_t)row * DMM;
    const float* qr  = qin  + (size_t)row * DMM;
    float v0 = ctx[tid]       + qr[tid];
    float v1 = ctx[tid + 256] + qr[tid + 256];
    int lane = tid & 31, w = tid >> 5;
    float s = v0 + v1;
#pragma unroll
    for (int o = 16; o; o >>= 1) s += __shfl_xor_sync(0xffffffffu, s, o);
    if (lane == 0) sm[w] = s;
    __syncthreads();
    float mean = (sm[0]+sm[1]+sm[2]+sm[3]+sm[4]+sm[5]+sm[6]+sm[7]) * (1.0f / DMM);
    float d0 = v0 - mean, d1 = v1 - mean;
    float s2 = d0*d0 + d1*d1;
#pragma unroll
    for (int o = 16; o; o >>= 1) s2 += __shfl_xor_sync(0xffffffffu, s2, o);
    if (lane == 0) sm2[w] = s2;
    __syncthreads();
    float var = (sm2[0]+sm2[1]+sm2[2]+sm2[3]+sm2[4]+sm2[5]+sm2[6]+sm2[7]) * (1.0f / DMM);
    float invstd = rsqrtf(var + LN_EPS);
    out[(size_t)row*DMM + tid]       = d0 * invstd * gamma[tid]       + beta[tid];
    out[(size_t)row*DMM + tid + 256] = d1 * invstd * gamma[tid + 256] + beta[tid + 256];
}

// ---------------- launch ----------------
extern "C" void kernel_launch(void* const* d_in, const int* in_sizes, int n_in,
                              void* d_out, int out_size)
{
    const float* q     = (const float*)d_in[0];
    const float* k     = (const float*)d_in[1];
    const float* v     = (const float*)d_in[2];
    const float* Wq    = (const float*)d_in[3];
    const float* bq    = (const float*)d_in[4];
    const float* Wk    = (const float*)d_in[5];
    const float* bk    = (const float*)d_in[6];
    const float* Wv    = (const float*)d_in[7];
    const float* bv    = (const float*)d_in[8];
    const float* gamma = (const float*)d_in[9];
    const float* beta  = (const float*)d_in[10];
    const int*   ridx  = (const int*)d_in[11];
    float* out      = (float*)d_out;
    float* out_attn = out + (size_t)Bb * Ll * DMM;

    // device-global symbol addresses (host-side)
    __nv_bfloat16 *qh, *ql, *kh, *kl, *vh, *vl, *wqh, *wql, *wkh, *wkl, *wvh, *wvl;
    cudaGetSymbolAddress((void**)&qh,  g_qh);  cudaGetSymbolAddress((void**)&ql,  g_ql);
    cudaGetSymbolAddress((void**)&kh,  g_kh);  cudaGetSymbolAddress((void**)&kl,  g_kl);
    cudaGetSymbolAddress((void**)&vh,  g_vh);  cudaGetSymbolAddress((void**)&vl,  g_vl);
    cudaGetSymbolAddress((void**)&wqh, g_Wqh); cudaGetSymbolAddress((void**)&wql, g_Wql);
    cudaGetSymbolAddress((void**)&wkh, g_Wkh); cudaGetSymbolAddress((void**)&wkl, g_Wkl);
    cudaGetSymbolAddress((void**)&wvh, g_Wvh); cudaGetSymbolAddress((void**)&wvl, g_Wvl);

    const int nA4 = (Bb*Ll*DMM) / 4;     // 524288
    const int nW4 = (DMM*DMM) / 4;       // 65536
    split_kernel<<<(nA4 + 255)/256, 256>>>(q,  qh,  ql,  nA4);
    split_kernel<<<(nA4 + 255)/256, 256>>>(k,  kh,  kl,  nA4);
    split_kernel<<<(nA4 + 255)/256, 256>>>(v,  vh,  vl,  nA4);
    split_kernel<<<(nW4 + 255)/256, 256>>>(Wq, wqh, wql, nW4);
    split_kernel<<<(nW4 + 255)/256, 256>>>(Wk, wkh, wkl, nW4);
    split_kernel<<<(nW4 + 255)/256, 256>>>(Wv, wvh, wvl, nW4);

    dim3 gg(DMM / 64, (Bb * Ll) / 128, 3);    // (8, 32, 3)
    gemm_tc_kernel<<<gg, 256>>>(bq, bk, bv);

    vmean_part_kernel<<<Bb * 16, DMM>>>();
    vmean_reduce_kernel<<<Bb, DMM>>>();
    fill_ctx_kernel<<<(Bb * Ll * DMM) / 256, 256>>>();

    measure_kernel<<<(Bb * Hh * Ll) / 8, 256>>>(ridx);
    topk_kernel<<<Bb * Hh, 256>>>();

    attn_kernel<<<Bb * Hh * 10, 256>>>(out_attn);

    ln_kernel<<<Bb * Ll, 256>>>(q, gamma, beta, out);
}

// round 4
// speedup vs baseline: 1.6952x; 1.3914x over previous
#include <cuda_runtime.h>
#include <cuda_bf16.h>
#include <math.h>
#include <stdint.h>

#define Bb 2
#define Ll 2048
#define DMM 512
#define Hh 8
#define Dd 64
#define NUMK 40
#define NUMQ 40
#define LN_EPS 1e-5f

// ---------------- scratch (static device globals; no allocs allowed) ----------------
__device__ __align__(256) float g_qp[Bb*Ll*DMM];
__device__ __align__(256) float g_kp[Bb*Ll*DMM];
__device__ __align__(256) float g_vp[Bb*Ll*DMM];
__device__ __align__(256) float g_ctx[Bb*Ll*DMM];
__device__ __align__(256) float g_measure[Bb*Hh*Ll];
__device__ __align__(256) float g_vpart[Bb*64*DMM];
__device__ __align__(256) float g_vmean[Bb*DMM];
__device__ __align__(256) int   g_qidx[Bb*Hh*NUMQ];
// W transposed + bf16 hi/lo split: [which][N][K]
__device__ __align__(256) __nv_bfloat16 g_Wth[3*DMM*DMM];
__device__ __align__(256) __nv_bfloat16 g_Wtl[3*DMM*DMM];

// ============================ helpers ============================
__device__ __forceinline__ uint32_t smem_u32(const void* p) {
    uint32_t a;
    asm("{ .reg .u64 t; cvta.to.shared.u64 t, %1; cvt.u32.u64 %0, t; }" : "=r"(a) : "l"(p));
    return a;
}
#define SWZ128(off) ((off) ^ (((off) >> 3) & 0x70))

#define STS128(addr, a, b, c, d) \
    asm volatile("st.shared.v4.b32 [%0], {%1, %2, %3, %4};" \
                 :: "r"(addr), "r"(a), "r"(b), "r"(c), "r"(d) : "memory")

__device__ __forceinline__ void ldsm4(uint32_t& r0, uint32_t& r1, uint32_t& r2, uint32_t& r3,
                                      uint32_t addr) {
    asm volatile("ldmatrix.sync.aligned.m8n8.x4.shared.b16 {%0,%1,%2,%3}, [%4];"
                 : "=r"(r0), "=r"(r1), "=r"(r2), "=r"(r3) : "r"(addr));
}
__device__ __forceinline__ void mma16816(float* c, const uint32_t* a, uint32_t b0, uint32_t b1) {
    asm volatile(
        "mma.sync.aligned.m16n8k16.row.col.f32.bf16.bf16.f32 "
        "{%0,%1,%2,%3}, {%4,%5,%6,%7}, {%8,%9}, {%0,%1,%2,%3};"
        : "+f"(c[0]), "+f"(c[1]), "+f"(c[2]), "+f"(c[3])
        : "r"(a[0]), "r"(a[1]), "r"(a[2]), "r"(a[3]), "r"(b0), "r"(b1));
}

__device__ __forceinline__ void split2(float a, float b, uint32_t& h, uint32_t& l) {
    __nv_bfloat16 ha = __float2bfloat16(a), hb = __float2bfloat16(b);
    __nv_bfloat16 la = __float2bfloat16(a - __bfloat162float(ha));
    __nv_bfloat16 lb = __float2bfloat16(b - __bfloat162float(hb));
    __nv_bfloat162 hh(ha, hb), ll(la, lb);
    h = *reinterpret_cast<uint32_t*>(&hh);
    l = *reinterpret_cast<uint32_t*>(&ll);
}

// ---------------- W transpose + bf16 split: Wt[n][k] = W[k][n] ----------------
__global__ void wsplit_t_kernel(const float* __restrict__ Wq,
                                const float* __restrict__ Wk,
                                const float* __restrict__ Wv)
{
    int which = blockIdx.z;
    const float* W = (which == 0) ? Wq : (which == 1) ? Wk : Wv;
    __nv_bfloat16* Th = g_Wth + (size_t)which * DMM * DMM;
    __nv_bfloat16* Tl = g_Wtl + (size_t)which * DMM * DMM;
    __shared__ float tile[32][33];
    int n0 = blockIdx.x * 32, k0 = blockIdx.y * 32;
    int x = threadIdx.x, y = threadIdx.y;   // 32 x 8
#pragma unroll
    for (int yy = 0; yy < 32; yy += 8)
        tile[y + yy][x] = W[(size_t)(k0 + y + yy) * DMM + n0 + x];
    __syncthreads();
#pragma unroll
    for (int yy = 0; yy < 32; yy += 8) {
        int n = n0 + y + yy;
        float f = tile[x][y + yy];           // = W[k0+x][n]
        __nv_bfloat16 h = __float2bfloat16(f);
        Th[(size_t)n * DMM + k0 + x] = h;
        Tl[(size_t)n * DMM + k0 + x] = __float2bfloat16(f - __bfloat162float(h));
    }
}

// ---------------- HMMA GEMM: C[4096,512] = A @ W + bias (3-term bf16 split) ----------------
// CTA tile M=128,N=128,BK=64. 8 warps of 64x32. Smem: 4 tiles of 128x64 bf16 (16KB each).
#define OFF_AH 0
#define OFF_AL 16384
#define OFF_BH 32768
#define OFF_BL 49152

__global__ void __launch_bounds__(256, 1)
gemm_tc_kernel(const float* __restrict__ qin, const float* __restrict__ kin,
               const float* __restrict__ vin,
               const float* __restrict__ bq, const float* __restrict__ bk,
               const float* __restrict__ bv)
{
    extern __shared__ char dsm[];

    int which = blockIdx.z;
    const float* A    = (which == 0) ? qin : (which == 1) ? kin : vin;
    const float* bias = (which == 0) ? bq  : (which == 1) ? bk  : bv;
    float* C          = (which == 0) ? g_qp : (which == 1) ? g_kp : g_vp;
    const __nv_bfloat16* Bh = g_Wth + (size_t)which * DMM * DMM;
    const __nv_bfloat16* Bl = g_Wtl + (size_t)which * DMM * DMM;

    int tid = threadIdx.x, wid = tid >> 5, lane = tid & 31;
    int m0 = blockIdx.y * 128, n0 = blockIdx.x * 128;
    int wm = wid & 1, wn = wid >> 1;          // warp tile: rows wm*64, cols wn*32

    uint32_t sb = (smem_u32(dsm) + 1023u) & ~1023u;

    // staging geometry: 1024 (row, 16B-chunk) pairs over 256 threads
    uint32_t soff[4];
    int rr[4], cc[4];
#pragma unroll
    for (int jj = 0; jj < 4; jj++) {
        int i = tid + 256 * jj;
        rr[jj] = i >> 3;
        cc[jj] = i & 7;
        soff[jj] = SWZ128((uint32_t)(rr[jj] * 128 + cc[jj] * 16));
    }

    // ldmatrix base offsets (per thread), A tiles: row = wm*64 + mt*16 + (lane&15)
    uint32_t a_off[4], b_off[2];
#pragma unroll
    for (int mt = 0; mt < 4; mt++) {
        int r = wm * 64 + mt * 16 + (lane & 15);
        a_off[mt] = (uint32_t)(r * 128) ;   // chunk added per-ks
    }
#pragma unroll
    for (int bt = 0; bt < 2; bt++) {
        int r = wn * 32 + bt * 16 + (lane & 15);
        b_off[bt] = (uint32_t)(r * 128);
    }
    int lhalf = lane >> 4;   // 0/1 -> extra 16B chunk

    float acc[4][4][4];
#pragma unroll
    for (int i = 0; i < 4; i++)
#pragma unroll
        for (int j = 0; j < 4; j++)
#pragma unroll
            for (int c = 0; c < 4; c++) acc[i][j][c] = 0.f;

    float4 fa[8];
    uint4 vbh[4], vbl[4];

    // prologue: global load k-tile 0
#pragma unroll
    for (int jj = 0; jj < 4; jj++) {
        const float* pa = A + (size_t)(m0 + rr[jj]) * DMM + cc[jj] * 8;
        fa[2*jj]   = *(const float4*)pa;
        fa[2*jj+1] = *(const float4*)(pa + 4);
        vbh[jj] = *(const uint4*)(Bh + (size_t)(n0 + rr[jj]) * DMM + cc[jj] * 8);
        vbl[jj] = *(const uint4*)(Bl + (size_t)(n0 + rr[jj]) * DMM + cc[jj] * 8);
    }

    for (int kt = 0; kt < 8; kt++) {
        // store staged tile
#pragma unroll
        for (int jj = 0; jj < 4; jj++) {
            uint32_t h0,h1,h2,h3,l0,l1,l2,l3;
            split2(fa[2*jj].x,   fa[2*jj].y,   h0, l0);
            split2(fa[2*jj].z,   fa[2*jj].w,   h1, l1);
            split2(fa[2*jj+1].x, fa[2*jj+1].y, h2, l2);
            split2(fa[2*jj+1].z, fa[2*jj+1].w, h3, l3);
            STS128(sb + OFF_AH + soff[jj], h0, h1, h2, h3);
            STS128(sb + OFF_AL + soff[jj], l0, l1, l2, l3);
            STS128(sb + OFF_BH + soff[jj], vbh[jj].x, vbh[jj].y, vbh[jj].z, vbh[jj].w);
            STS128(sb + OFF_BL + soff[jj], vbl[jj].x, vbl[jj].y, vbl[jj].z, vbl[jj].w);
        }
        __syncthreads();

        // prefetch next k-tile while mma runs
        if (kt < 7) {
            int kb = (kt + 1) * 64;
#pragma unroll
            for (int jj = 0; jj < 4; jj++) {
                const float* pa = A + (size_t)(m0 + rr[jj]) * DMM + kb + cc[jj] * 8;
                fa[2*jj]   = *(const float4*)pa;
                fa[2*jj+1] = *(const float4*)(pa + 4);
                vbh[jj] = *(const uint4*)(Bh + (size_t)(n0 + rr[jj]) * DMM + kb + cc[jj] * 8);
                vbl[jj] = *(const uint4*)(Bl + (size_t)(n0 + rr[jj]) * DMM + kb + cc[jj] * 8);
            }
        }

        // mma over 4 k-steps of 16
#pragma unroll
        for (int ks = 0; ks < 4; ks++) {
            uint32_t chunk = (uint32_t)((2*ks + lhalf) * 16);
            uint32_t ah[4][4], al[4][4];
#pragma unroll
            for (int mt = 0; mt < 4; mt++) {
                uint32_t sw = SWZ128(a_off[mt] + chunk);
                ldsm4(ah[mt][0], ah[mt][1], ah[mt][2], ah[mt][3], sb + OFF_AH + sw);
                ldsm4(al[mt][0], al[mt][1], al[mt][2], al[mt][3], sb + OFF_AL + sw);
            }
            uint32_t bh[2][4], bl[2][4];
#pragma unroll
            for (int bt = 0; bt < 2; bt++) {
                uint32_t sw = SWZ128(b_off[bt] + chunk);
                ldsm4(bh[bt][0], bh[bt][1], bh[bt][2], bh[bt][3], sb + OFF_BH + sw);
                ldsm4(bl[bt][0], bl[bt][1], bl[bt][2], bl[bt][3], sb + OFF_BL + sw);
            }
#pragma unroll
            for (int mt = 0; mt < 4; mt++) {
#pragma unroll
                for (int nt = 0; nt < 4; nt++) {
                    int bt = nt >> 1, hi = nt & 1;
                    uint32_t bh0 = bh[bt][hi],   bh1 = bh[bt][hi+2];
                    uint32_t bl0 = bl[bt][hi],   bl1 = bl[bt][hi+2];
                    mma16816(acc[mt][nt], ah[mt], bh0, bh1);
                    mma16816(acc[mt][nt], ah[mt], bl0, bl1);
                    mma16816(acc[mt][nt], al[mt], bh0, bh1);
                }
            }
        }
        __syncthreads();
    }

    // epilogue: c0,c1 -> (row=lane>>2, col=(lane&3)*2); c2,c3 -> row+8
#pragma unroll
    for (int mt = 0; mt < 4; mt++) {
        int mrow = m0 + wm*64 + mt*16 + (lane >> 2);
#pragma unroll
        for (int nt = 0; nt < 4; nt++) {
            int ncol = n0 + wn*32 + nt*8 + (lane & 3)*2;
            float b0 = bias[ncol], b1 = bias[ncol + 1];
            float2 v0 = make_float2(acc[mt][nt][0] + b0, acc[mt][nt][1] + b1);
            float2 v1 = make_float2(acc[mt][nt][2] + b0, acc[mt][nt][3] + b1);
            *(float2*)(C + (size_t)mrow * DMM + ncol)       = v0;
            *(float2*)(C + (size_t)(mrow + 8) * DMM + ncol) = v1;
        }
    }
}

// ---------------- v_mean (two-stage, deterministic) ----------------
__global__ void vmean_part_kernel() {
    int blk = blockIdx.x;               // 128
    int b = blk >> 6, j = blk & 63;
    int c = threadIdx.x;                // 512
    float s = 0.f;
    int base = j * 32;
    for (int l = base; l < base + 32; l++) s += g_vp[((size_t)b*Ll + l)*DMM + c];
    g_vpart[(size_t)blk*DMM + c] = s;
}
__global__ void vmean_reduce_kernel() {
    int b = blockIdx.x; int c = threadIdx.x;
    float s = 0.f;
    for (int j = 0; j < 64; j++) s += g_vpart[((size_t)b*64 + j)*DMM + c];
    g_vmean[b*DMM + c] = s * (1.0f / Ll);
}

__global__ void fill_ctx_kernel() {
    int idx = blockIdx.x * blockDim.x + threadIdx.x;
    int c = idx & (DMM - 1);
    int b = idx >> 20;
    g_ctx[idx] = g_vmean[b*DMM + c];
}

// ---------------- pre + measure: one warp per (b,l), all 8 heads ----------------
__global__ __launch_bounds__(256) void measure_kernel(const int* __restrict__ ridx) {
    int gw = (blockIdx.x * blockDim.x + threadIdx.x) >> 5;   // 0..4095
    int lane = threadIdx.x & 31;
    if (gw >= Bb * Ll) return;
    int l = gw & (Ll - 1);
    int b = gw >> 11;
    const float4* qrow = (const float4*)&g_qp[((size_t)b*Ll + l) * DMM];
    float4 q0 = qrow[lane*4+0], q1 = qrow[lane*4+1], q2 = qrow[lane*4+2], q3 = qrow[lane*4+3];
    int i0 = ridx[l*NUMK + lane];
    int i1 = ridx[l*NUMK + 32 + (lane & 7)];
    float mx = -INFINITY, sm = 0.f;
#pragma unroll 4
    for (int j = 0; j < NUMK; j++) {
        int ki = (j < 32) ? __shfl_sync(0xffffffffu, i0, j)
                          : __shfl_sync(0xffffffffu, i1, j - 32);
        const float4* kr = (const float4*)&g_kp[((size_t)b*Ll + ki) * DMM];
        float4 k0 = kr[lane*4+0], k1 = kr[lane*4+1], k2 = kr[lane*4+2], k3 = kr[lane*4+3];
        float p = q0.x*k0.x + q0.y*k0.y + q0.z*k0.z + q0.w*k0.w
                + q1.x*k1.x + q1.y*k1.y + q1.z*k1.z + q1.w*k1.w
                + q2.x*k2.x + q2.y*k2.y + q2.z*k2.z + q2.w*k2.w
                + q3.x*k3.x + q3.y*k3.y + q3.z*k3.z + q3.w*k3.w;
        p += __shfl_xor_sync(0xffffffffu, p, 1);
        p += __shfl_xor_sync(0xffffffffu, p, 2);
        mx = fmaxf(mx, p);
        sm += p;
    }
    if ((lane & 3) == 0) {
        int h = lane >> 2;
        g_measure[((size_t)b*Hh + h)*Ll + l] = mx - sm * (1.0f / Ll);
    }
}

// ---------------- exact top-40 per (b,h), register-resident ----------------
__global__ __launch_bounds__(256) void topk_kernel() {
    int bh = blockIdx.x, t = threadIdx.x;
    float v[8];
    const float* src = g_measure + (size_t)bh * Ll;
#pragma unroll
    for (int m = 0; m < 8; m++) v[m] = src[t + 256*m];
    __shared__ float swv[8];
    __shared__ int   swi[8];
    __shared__ int   s_best;
    for (int s = 0; s < NUMQ; s++) {
        float bv = v[0]; int bi = t;
#pragma unroll
        for (int m = 1; m < 8; m++) {
            int i = t + 256*m;
            if (v[m] > bv || (v[m] == bv && i < bi)) { bv = v[m]; bi = i; }
        }
#pragma unroll
        for (int o = 16; o; o >>= 1) {
            float ov = __shfl_xor_sync(0xffffffffu, bv, o);
            int   oi = __shfl_xor_sync(0xffffffffu, bi, o);
            if (ov > bv || (ov == bv && oi < bi)) { bv = ov; bi = oi; }
        }
        if ((t & 31) == 0) { swv[t >> 5] = bv; swi[t >> 5] = bi; }
        __syncthreads();
        if (t == 0) {
            float rv = swv[0]; int ri = swi[0];
#pragma unroll
            for (int w = 1; w < 8; w++)
                if (swv[w] > rv || (swv[w] == rv && swi[w] < ri)) { rv = swv[w]; ri = swi[w]; }
            g_qidx[bh*NUMQ + s] = ri;
            s_best = ri;
        }
        __syncthreads();
        int ib = s_best;
        if ((ib & 255) == t) v[ib >> 8] = -INFINITY;
    }
}

// ---------------- attention: block per (b,h,group-of-4-q) ----------------
__global__ __launch_bounds__(256) void attn_kernel(float* __restrict__ out_attn) {
    int blk = blockIdx.x;
    int g = blk % 10;
    int h = (blk / 10) % Hh;
    int b = blk / (10 * Hh);
    __shared__ float qs[4][Dd];
    __shared__ float sc[4][Ll];
    __shared__ float red[8];
    __shared__ float pvs[4][4][Dd];
    __shared__ int qix[4];
    int tid = threadIdx.x;
    int lane = tid & 31, w = tid >> 5;
    if (tid < 4) qix[tid] = g_qidx[(b*Hh + h)*NUMQ + g*4 + tid];
    __syncthreads();
    {
        int qq = tid >> 6, d = tid & 63;
        qs[qq][d] = g_qp[((size_t)b*Ll + qix[qq])*DMM + h*Dd + d];
    }
    __syncthreads();
    const float scale = 0.125f;
    for (int j = w; j < Ll; j += 8) {
        const float2 kv = *(const float2*)&g_kp[((size_t)b*Ll + j)*DMM + h*Dd + lane*2];
        float p0 = kv.x*qs[0][lane*2] + kv.y*qs[0][lane*2+1];
        float p1 = kv.x*qs[1][lane*2] + kv.y*qs[1][lane*2+1];
        float p2 = kv.x*qs[2][lane*2] + kv.y*qs[2][lane*2+1];
        float p3 = kv.x*qs[3][lane*2] + kv.y*qs[3][lane*2+1];
#pragma unroll
        for (int o = 16; o; o >>= 1) {
            p0 += __shfl_xor_sync(0xffffffffu, p0, o);
            p1 += __shfl_xor_sync(0xffffffffu, p1, o);
            p2 += __shfl_xor_sync(0xffffffffu, p2, o);
            p3 += __shfl_xor_sync(0xffffffffu, p3, o);
        }
        if (lane == 0) {
            sc[0][j] = p0 * scale; sc[1][j] = p1 * scale;
            sc[2][j] = p2 * scale; sc[3][j] = p3 * scale;
        }
    }
    __syncthreads();
#pragma unroll
    for (int q = 0; q < 4; q++) {
        float m = -INFINITY;
        for (int j = tid; j < Ll; j += 256) m = fmaxf(m, sc[q][j]);
#pragma unroll
        for (int o = 16; o; o >>= 1) m = fmaxf(m, __shfl_xor_sync(0xffffffffu, m, o));
        if (lane == 0) red[w] = m;
        __syncthreads();
        m = fmaxf(fmaxf(fmaxf(red[0],red[1]),fmaxf(red[2],red[3])),
                  fmaxf(fmaxf(red[4],red[5]),fmaxf(red[6],red[7])));
        __syncthreads();
        float s = 0.f;
        for (int j = tid; j < Ll; j += 256) { float e = expf(sc[q][j] - m); sc[q][j] = e; s += e; }
#pragma unroll
        for (int o = 16; o; o >>= 1) s += __shfl_xor_sync(0xffffffffu, s, o);
        if (lane == 0) red[w] = s;
        __syncthreads();
        float inv = 1.0f / (red[0]+red[1]+red[2]+red[3]+red[4]+red[5]+red[6]+red[7]);
        size_t aoff = ((size_t)(b*Hh + h)*NUMQ + g*4 + q) * Ll;
        for (int j = tid; j < Ll; j += 256) {
            float p = sc[q][j] * inv;
            sc[q][j] = p;
            out_attn[aoff + j] = p;
        }
        __syncthreads();
    }
    int d = tid & 63, part = tid >> 6;
    float a0 = 0.f, a1 = 0.f, a2 = 0.f, a3 = 0.f;
    int j0 = part * 512;
    for (int j = j0; j < j0 + 512; j++) {
        float v = g_vp[((size_t)b*Ll + j)*DMM + h*Dd + d];
        a0 += sc[0][j]*v; a1 += sc[1][j]*v; a2 += sc[2][j]*v; a3 += sc[3][j]*v;
    }
    pvs[part][0][d] = a0; pvs[part][1][d] = a1;
    pvs[part][2][d] = a2; pvs[part][3][d] = a3;
    __syncthreads();
    if (part == 0) {
#pragma unroll
        for (int q = 0; q < 4; q++) {
            float r = pvs[0][q][d] + pvs[1][q][d] + pvs[2][q][d] + pvs[3][q][d];
            g_ctx[((size_t)b*Ll + qix[q])*DMM + h*Dd + d] = r;
        }
    }
}

// ---------------- residual + layernorm ----------------
__global__ __launch_bounds__(256) void ln_kernel(const float* __restrict__ qin,
                                                 const float* __restrict__ gamma,
                                                 const float* __restrict__ beta,
                                                 float* __restrict__ out)
{
    int row = blockIdx.x;
    int tid = threadIdx.x;
    __shared__ float sm[8], sm2[8];
    const float* ctx = g_ctx + (size_t)row * DMM;
    const float* qr  = qin  + (size_t)row * DMM;
    float v0 = ctx[tid]       + qr[tid];
    float v1 = ctx[tid + 256] + qr[tid + 256];
    int lane = tid & 31, w = tid >> 5;
    float s = v0 + v1;
#pragma unroll
    for (int o = 16; o; o >>= 1) s += __shfl_xor_sync(0xffffffffu, s, o);
    if (lane == 0) sm[w] = s;
    __syncthreads();
    float mean = (sm[0]+sm[1]+sm[2]+sm[3]+sm[4]+sm[5]+sm[6]+sm[7]) * (1.0f / DMM);
    float d0 = v0 - mean, d1 = v1 - mean;
    float s2 = d0*d0 + d1*d1;
#pragma unroll
    for (int o = 16; o; o >>= 1) s2 += __shfl_xor_sync(0xffffffffu, s2, o);
    if (lane == 0) sm2[w] = s2;
    __syncthreads();
    float var = (sm2[0]+sm2[1]+sm2[2]+sm2[3]+sm2[4]+sm2[5]+sm2[6]+sm2[7]) * (1.0f / DMM);
    float invstd = rsqrtf(var + LN_EPS);
    out[(size_t)row*DMM + tid]       = d0 * invstd * gamma[tid]       + beta[tid];
    out[(size_t)row*DMM + tid + 256] = d1 * invstd * gamma[tid + 256] + beta[tid + 256];
}

// ---------------- launch ----------------
extern "C" void kernel_launch(void* const* d_in, const int* in_sizes, int n_in,
                              void* d_out, int out_size)
{
    const float* q     = (const float*)d_in[0];
    const float* k     = (const float*)d_in[1];
    const float* v     = (const float*)d_in[2];
    const float* Wq    = (const float*)d_in[3];
    const float* bq    = (const float*)d_in[4];
    const float* Wk    = (const float*)d_in[5];
    const float* bk    = (const float*)d_in[6];
    const float* Wv    = (const float*)d_in[7];
    const float* bv    = (const float*)d_in[8];
    const float* gamma = (const float*)d_in[9];
    const float* beta  = (const float*)d_in[10];
    const int*   ridx  = (const int*)d_in[11];
    float* out      = (float*)d_out;
    float* out_attn = out + (size_t)Bb * Ll * DMM;

    static bool attr_set = false;
    if (!attr_set) {
        cudaFuncSetAttribute(gemm_tc_kernel,
                             cudaFuncAttributeMaxDynamicSharedMemorySize, 66560);
        attr_set = true;
    }

    wsplit_t_kernel<<<dim3(16, 16, 3), dim3(32, 8)>>>(Wq, Wk, Wv);

    gemm_tc_kernel<<<dim3(4, 32, 3), 256, 66560>>>(q, k, v, bq, bk, bv);

    vmean_part_kernel<<<128, DMM>>>();
    vmean_reduce_kernel<<<Bb, DMM>>>();
    fill_ctx_kernel<<<(Bb * Ll * DMM) / 256, 256>>>();

    measure_kernel<<<(Bb * Ll) / 8, 256>>>(ridx);
    topk_kernel<<<Bb * Hh, 256>>>();

    attn_kernel<<<Bb * Hh * 10, 256>>>(out_attn);

    ln_kernel<<<Bb * Ll, 256>>>(q, gamma, beta, out);
}